// round 7
// baseline (speedup 1.0000x reference)
#include <cuda_runtime.h>
#include <cstdint>
#include <math.h>

#define N_NODES 50000
#define N_EDGES 600000
#define HID 128

// Scratch
__device__ float g_h[(size_t)N_NODES * HID];    // x @ fc1_w.T
__device__ float g_agg[(size_t)N_NODES * HID];  // scatter-add accumulator

// Shifted softplus with 1 MUFU: t = exp(-|x|) in (0,1];
// log1p(t) - ln2 = poly(t - 0.5) via Taylor of log(1.5+s), deg 9,
// |err| <= 1.7e-6 abs. FMA-pipe work instead of MUFU.LG2.
__device__ __forceinline__ float sspf(float x) {
    float t = __expf(-fabsf(x));
    float s = t - 0.5f;
    float p = 0.00289026f;                 // +1/(9*1.5^9)
    p = fmaf(p, s, -0.00487730f);          // -1/(8*1.5^8)
    p = fmaf(p, s, 0.00836110f);           // +1/(7*1.5^7)
    p = fmaf(p, s, -0.01463192f);          // -1/(6*1.5^6)
    p = fmaf(p, s, 0.02633745f);           // +1/(5*1.5^5)
    p = fmaf(p, s, -0.04938272f);          // -1/(4*1.5^4)
    p = fmaf(p, s, 0.09876543f);           // +1/(3*1.5^3)
    p = fmaf(p, s, -0.22222222f);          // -1/(2*1.5^2)
    p = fmaf(p, s, 0.66666667f);           // +1/1.5
    p = fmaf(p, s, -0.28768207f);          // log(1.5) - ln(2)
    return fmaxf(x, 0.0f) + p;
}

__device__ __forceinline__ float to_tf32(float x) {
    float r;
    asm("cvt.rna.tf32.f32 %0, %1;" : "=f"(r) : "f"(x));
    return r;
}

__device__ __forceinline__ void mma16n8k8(float c[4], const uint32_t a[4],
                                          const uint32_t b[2]) {
    asm volatile(
        "mma.sync.aligned.m16n8k8.row.col.f32.tf32.tf32.f32 "
        "{%0,%1,%2,%3}, {%4,%5,%6,%7}, {%8,%9}, {%0,%1,%2,%3};"
        : "+f"(c[0]), "+f"(c[1]), "+f"(c[2]), "+f"(c[3])
        : "r"(a[0]), "r"(a[1]), "r"(a[2]), "r"(a[3]), "r"(b[0]), "r"(b[1]));
}

__device__ __forceinline__ void red_add_v4(float* addr, float4 v) {
    asm volatile("red.global.add.v4.f32 [%0], {%1, %2, %3, %4};"
                 :: "l"(addr), "f"(v.x), "f"(v.y), "f"(v.z), "f"(v.w) : "memory");
}

#define BAR_GRP(id) asm volatile("bar.sync %0, 64;" :: "r"(id) : "memory")

#define NT 512       // threads per CTA: 16 warps = 8 groups x 2 warps
#define SA 132       // padded fp32 stride of the A tile

// ==========================================================================
// Packed weight layout (proven): Wp[n*128 + wcol(k,n)] = tf32(W[n][k])
// ==========================================================================
__device__ __forceinline__ int wcol(int k, int n) {
    int pk = (k & ~15) | ((k & 3) << 2) | ((k >> 2) & 3);
    return pk ^ ((n & 1) << 4);
}

__device__ __forceinline__ void load_weights_packed(const float* __restrict__ G,
                                                    float* __restrict__ Wp) {
    for (int idx = threadIdx.x; idx < 128 * 32; idx += NT) {
        int n = idx >> 5, t = idx & 31;
        float4 v = *(const float4*)&G[n * 128 + t * 4];
        float vv[4] = {to_tf32(v.x), to_tf32(v.y), to_tf32(v.z), to_tf32(v.w)};
        #pragma unroll
        for (int i = 0; i < 4; ++i) Wp[n * 128 + wcol(t * 4 + i, n)] = vv[i];
    }
}

// Group-local load: 16 rows of a row-major [*,128] tensor into As rows
// srow0..+15 (tf32-rounded). 64 threads (tg).
__device__ __forceinline__ void load_rows16(const float* __restrict__ G, int grow0,
                                            int nrows, float* __restrict__ Sm,
                                            int srow0, int tg) {
    #pragma unroll
    for (int i = 0; i < 8; ++i) {
        int idx = tg + i * 64;   // 0..511 float4 slots
        int r = idx >> 5;
        int q = idx & 31;
        float4 v = make_float4(0.f, 0.f, 0.f, 0.f);
        if (grow0 + r < nrows) v = *(const float4*)&G[(size_t)(grow0 + r) * 128 + q * 4];
        v.x = to_tf32(v.x); v.y = to_tf32(v.y); v.z = to_tf32(v.z); v.w = to_tf32(v.w);
        *(float4*)&Sm[(srow0 + r) * SA + q * 4] = v;
    }
}

// 16x128x64 warp GEMM (rows mb*16..+15, cols nb*64..+63): acc += A * Wp^T
__device__ __forceinline__ void warp_gemm(const float* __restrict__ As,
                                          const float* __restrict__ Wp,
                                          float acc[8][4], int mb, int nb) {
    const int lid = threadIdx.x & 31;
    const int gr = lid >> 2;
    const int gc = lid & 3;
    const float* abase = As + (mb * 16 + gr) * SA + gc;
    const int nrow0 = nb * 64 + gr;
    const int nxor = (gr & 1) << 4;

    #pragma unroll
    for (int c = 0; c < 8; ++c) {
        const int k0 = c * 16;
        const float* ap0 = abase + k0;
        const float* ap1 = ap0 + 8 * SA;
        uint32_t a0[4], a1[4];
        a0[0] = __float_as_uint(ap0[0]);
        a0[1] = __float_as_uint(ap1[0]);
        a0[2] = __float_as_uint(ap0[4]);
        a0[3] = __float_as_uint(ap1[4]);
        a1[0] = __float_as_uint(ap0[8]);
        a1[1] = __float_as_uint(ap1[8]);
        a1[2] = __float_as_uint(ap0[12]);
        a1[3] = __float_as_uint(ap1[12]);
        #pragma unroll
        for (int nj = 0; nj < 8; ++nj) {
            const int n = nrow0 + 8 * nj;
            float4 bv = *(const float4*)&Wp[n * 128 + ((k0 + gc * 4) ^ nxor)];
            uint32_t b0[2] = {__float_as_uint(bv.x), __float_as_uint(bv.y)};
            uint32_t b1[2] = {__float_as_uint(bv.z), __float_as_uint(bv.w)};
            mma16n8k8(acc[nj], a0, b0);
            mma16n8k8(acc[nj], a1, b1);
        }
    }
}

__device__ __forceinline__ void zero_acc8(float acc[8][4]) {
    #pragma unroll
    for (int nj = 0; nj < 8; ++nj)
        #pragma unroll
        for (int e = 0; e < 4; ++e) acc[nj][e] = 0.0f;
}

// ssp(acc + bias) -> As rows mb*16..+15, cols nb*64..+63
__device__ __forceinline__ void ssp_writeback(float* __restrict__ Sm,
                                              const float* __restrict__ bias,
                                              float acc[8][4], int mb, int nb,
                                              bool round_tf32) {
    const int lid = threadIdx.x & 31;
    const int gr = lid >> 2;
    const int gc = lid & 3;
    int r0 = mb * 16 + gr;
    #pragma unroll
    for (int nj = 0; nj < 8; ++nj) {
        int c0 = nb * 64 + nj * 8 + 2 * gc;
        float b0 = bias ? bias[c0] : 0.0f;
        float b1v = bias ? bias[c0 + 1] : 0.0f;
        float2 lo, hi;
        lo.x = sspf(acc[nj][0] + b0);
        lo.y = sspf(acc[nj][1] + b1v);
        hi.x = sspf(acc[nj][2] + b0);
        hi.y = sspf(acc[nj][3] + b1v);
        if (round_tf32) {
            lo.x = to_tf32(lo.x); lo.y = to_tf32(lo.y);
            hi.x = to_tf32(hi.x); hi.y = to_tf32(hi.y);
        }
        *(float2*)&Sm[r0 * SA + c0] = lo;
        *(float2*)&Sm[(r0 + 8) * SA + c0] = hi;
    }
}

// ==========================================================================
// Edge kernel: 8 independent 2-warp groups, per-group named barriers
// ==========================================================================
#define TILES_PER_CTA 8
#define EGRID 586

#define ESM_IDX 0
#define ESM_B1 256
#define ESM_B2 384
#define ESM_AS 512
#define ESM_W1 (512 + 128 * SA)
#define ESM_W2 (512 + 128 * SA + 16384)
#define ESM_FLOATS (512 + 128 * SA + 32768)

__global__ void __launch_bounds__(NT, 1)
edge_kernel(const float* __restrict__ ea, const int* __restrict__ ei,
            const float* __restrict__ fw1, const float* __restrict__ fb1,
            const float* __restrict__ fw2, const float* __restrict__ fb2) {
    extern __shared__ float sm[];
    int* src_s = (int*)&sm[ESM_IDX];
    int* dst_s = src_s + 128;
    float* b1s = &sm[ESM_B1];
    float* b2s = &sm[ESM_B2];
    float* As = &sm[ESM_AS];
    float* W1p = &sm[ESM_W1];
    float* W2p = &sm[ESM_W2];

    const int tid = threadIdx.x;
    const int mb = tid >> 6;          // group 0..7: rows mb*16..+15
    const int nb = (tid >> 5) & 1;    // warp-in-group: cols nb*64..+63
    const int tg = tid & 63;          // thread-in-group
    const int bar = mb + 1;           // named barrier ids 1..8

    load_weights_packed(fw1, W1p);
    load_weights_packed(fw2, W2p);
    if (tid < 128) {
        b1s[tid] = fb1[tid];
        b2s[tid] = fb2[tid];
    }
    __syncthreads();

    for (int it = 0; it < TILES_PER_CTA; ++it) {
        const int row0 = (blockIdx.x * TILES_PER_CTA + it) * 128;
        if (row0 >= N_EDGES) break;

        // group-local loads: 16 A rows + 16 index pairs
        load_rows16(ea, row0 + mb * 16, N_EDGES, As, mb * 16, tg);
        if (tg < 16) {
            int e = row0 + mb * 16 + tg;
            src_s[mb * 16 + tg] = (e < N_EDGES) ? ei[e] : 0;
            dst_s[mb * 16 + tg] = (e < N_EDGES) ? ei[N_EDGES + e] : 0;
        }
        BAR_GRP(bar);

        float acc[8][4];

        zero_acc8(acc);
        warp_gemm(As, W1p, acc, mb, nb);            // Y1 = ea @ W1^T
        BAR_GRP(bar);

        ssp_writeback(As, b1s, acc, mb, nb, true);  // Z = tf32(ssp(Y1+b1))
        BAR_GRP(bar);

        zero_acc8(acc);
        warp_gemm(As, W2p, acc, mb, nb);            // Y2 = Z @ W2^T
        BAR_GRP(bar);

        ssp_writeback(As, b2s, acc, mb, nb, false); // W = ssp(Y2+b2)
        BAR_GRP(bar);

        // epilogue: group's 16 rows; msg = h[src]*W; red.add -> agg[dst]
        {
            const int hw = tg >> 4;     // 0..3 -> 4 rows each
            const int l16 = tg & 15;
            #pragma unroll
            for (int j = 0; j < 4; ++j) {
                int m = mb * 16 + hw * 4 + j;
                int e = row0 + m;
                if (e < N_EDGES) {
                    int s = src_s[m];
                    int d = dst_s[m];
                    const float* wp = &As[m * SA + l16 * 8];
                    const float* hp = &g_h[(size_t)s * 128 + l16 * 8];
                    float* ap = &g_agg[(size_t)d * 128 + l16 * 8];
                    float4 w0 = *(const float4*)wp;
                    float4 w1 = *(const float4*)(wp + 4);
                    float4 h0 = *(const float4*)hp;
                    float4 h1 = *(const float4*)(hp + 4);
                    red_add_v4(ap, make_float4(w0.x * h0.x, w0.y * h0.y,
                                               w0.z * h0.z, w0.w * h0.w));
                    red_add_v4(ap + 4, make_float4(w1.x * h1.x, w1.y * h1.y,
                                                   w1.z * h1.z, w1.w * h1.w));
                }
            }
        }
        BAR_GRP(bar);  // As reads done before next tile's load
    }
}

// ==========================================================================
// Node h kernel (persistent, grouped): h = x @ fc1^T ; zero g_agg
// ==========================================================================
#define NODE_TILES 2
#define NODE_GRID 196   // 196*2 = 392 >= 391

#define NSM_AS 0
#define NSM_W (128 * SA)
#define NSM_FLOATS (128 * SA + 16384)

__global__ void __launch_bounds__(NT, 1)
node_h_kernel(const float* __restrict__ x, const float* __restrict__ fc1_w) {
    extern __shared__ float sm[];
    float* As = &sm[NSM_AS];
    float* Wp = &sm[NSM_W];

    const int tid = threadIdx.x;
    const int mb = tid >> 6;
    const int nb = (tid >> 5) & 1;
    const int tg = tid & 63;
    const int bar = mb + 1;
    const int lid = tid & 31;
    const int gr = lid >> 2;
    const int gc = lid & 3;

    load_weights_packed(fc1_w, Wp);
    __syncthreads();

    for (int it = 0; it < NODE_TILES; ++it) {
        const int row0 = (blockIdx.x * NODE_TILES + it) * 128;
        if (row0 >= N_NODES) break;

        load_rows16(x, row0 + mb * 16, N_NODES, As, mb * 16, tg);
        BAR_GRP(bar);

        float acc[8][4];
        zero_acc8(acc);
        warp_gemm(As, Wp, acc, mb, nb);

        int r0 = row0 + mb * 16 + gr;
        #pragma unroll
        for (int nj = 0; nj < 8; ++nj) {
            int c0 = nb * 64 + nj * 8 + 2 * gc;
            if (r0 < N_NODES)
                *(float2*)&g_h[(size_t)r0 * 128 + c0] =
                    make_float2(acc[nj][0], acc[nj][1]);
            if (r0 + 8 < N_NODES)
                *(float2*)&g_h[(size_t)(r0 + 8) * 128 + c0] =
                    make_float2(acc[nj][2], acc[nj][3]);
        }

        // zero g_agg for this group's 16 rows
        const float4 z4 = make_float4(0.f, 0.f, 0.f, 0.f);
        #pragma unroll
        for (int i = 0; i < 8; ++i) {
            int idx = tg + i * 64;
            int r = row0 + mb * 16 + (idx >> 5);
            int q = idx & 31;
            if (r < N_NODES) *(float4*)&g_agg[(size_t)r * 128 + q * 4] = z4;
        }
        BAR_GRP(bar);  // gemm reads done before next tile's As load
    }
}

// ==========================================================================
// Final kernel (persistent, grouped): out = ssp(agg @ s_w1^T) @ s_w2^T
// ==========================================================================
#define FSM_AS 0
#define FSM_W1 (128 * SA)
#define FSM_W2 (128 * SA + 16384)
#define FSM_FLOATS (128 * SA + 32768)

__global__ void __launch_bounds__(NT, 1)
final_kernel(const float* __restrict__ sw1, const float* __restrict__ sw2,
             float* __restrict__ out) {
    extern __shared__ float sm[];
    float* As = &sm[FSM_AS];
    float* W1p = &sm[FSM_W1];
    float* W2p = &sm[FSM_W2];

    const int tid = threadIdx.x;
    const int mb = tid >> 6;
    const int nb = (tid >> 5) & 1;
    const int tg = tid & 63;
    const int bar = mb + 1;
    const int lid = tid & 31;
    const int gr = lid >> 2;
    const int gc = lid & 3;

    load_weights_packed(sw1, W1p);
    load_weights_packed(sw2, W2p);
    __syncthreads();

    for (int it = 0; it < NODE_TILES; ++it) {
        const int row0 = (blockIdx.x * NODE_TILES + it) * 128;
        if (row0 >= N_NODES) break;

        load_rows16(g_agg, row0 + mb * 16, N_NODES, As, mb * 16, tg);
        BAR_GRP(bar);

        float acc[8][4];
        zero_acc8(acc);
        warp_gemm(As, W1p, acc, mb, nb);
        BAR_GRP(bar);

        ssp_writeback(As, (const float*)nullptr, acc, mb, nb, true);
        BAR_GRP(bar);

        zero_acc8(acc);
        warp_gemm(As, W2p, acc, mb, nb);

        int r0 = row0 + mb * 16 + gr;
        #pragma unroll
        for (int nj = 0; nj < 8; ++nj) {
            int c0 = nb * 64 + nj * 8 + 2 * gc;
            if (r0 < N_NODES)
                *(float2*)&out[(size_t)r0 * 128 + c0] =
                    make_float2(acc[nj][0], acc[nj][1]);
            if (r0 + 8 < N_NODES)
                *(float2*)&out[(size_t)(r0 + 8) * 128 + c0] =
                    make_float2(acc[nj][2], acc[nj][3]);
        }
        BAR_GRP(bar);  // gemm reads done before next tile's As load
    }
}

// ==========================================================================
extern "C" void kernel_launch(void* const* d_in, const int* in_sizes, int n_in,
                              void* d_out, int out_size) {
    const float* x = (const float*)d_in[0];
    const float* ea = (const float*)d_in[1];
    const int* ei = (const int*)d_in[2];
    const float* fc1w = (const float*)d_in[3];
    const float* fw1 = (const float*)d_in[4];
    const float* fb1 = (const float*)d_in[5];
    const float* fw2 = (const float*)d_in[6];
    const float* fb2 = (const float*)d_in[7];
    const float* sw1 = (const float*)d_in[8];
    const float* sw2 = (const float*)d_in[9];
    float* out = (float*)d_out;

    const size_t sh_edge = (size_t)ESM_FLOATS * sizeof(float);
    const size_t sh_node = (size_t)NSM_FLOATS * sizeof(float);
    const size_t sh_final = (size_t)FSM_FLOATS * sizeof(float);

    cudaFuncSetAttribute(edge_kernel, cudaFuncAttributeMaxDynamicSharedMemorySize, (int)sh_edge);
    cudaFuncSetAttribute(node_h_kernel, cudaFuncAttributeMaxDynamicSharedMemorySize, (int)sh_node);
    cudaFuncSetAttribute(final_kernel, cudaFuncAttributeMaxDynamicSharedMemorySize, (int)sh_final);

    node_h_kernel<<<NODE_GRID, NT, sh_node>>>(x, fc1w);
    edge_kernel<<<EGRID, NT, sh_edge>>>(ea, ei, fw1, fb1, fw2, fb2);
    final_kernel<<<NODE_GRID, NT, sh_final>>>(sw1, sw2, out);
}

// round 8
// speedup vs baseline: 1.2778x; 1.2778x over previous
#include <cuda_runtime.h>
#include <cuda_fp16.h>
#include <cstdint>
#include <math.h>

#define N_NODES 50000
#define N_EDGES 600000
#define HID 128

// Scratch
__device__ float g_h[(size_t)N_NODES * HID];    // x @ fc1_w.T
__device__ float g_agg[(size_t)N_NODES * HID];  // scatter-add accumulator

// Shifted softplus, 1 MUFU: t = exp(-|x|); log1p(t)-ln2 = poly(t-0.5)
// (deg-9 Taylor of log(1.5+s), |err| <= 1.7e-6 abs)
__device__ __forceinline__ float sspf(float x) {
    float t = __expf(-fabsf(x));
    float s = t - 0.5f;
    float p = 0.00289026f;
    p = fmaf(p, s, -0.00487730f);
    p = fmaf(p, s, 0.00836110f);
    p = fmaf(p, s, -0.01463192f);
    p = fmaf(p, s, 0.02633745f);
    p = fmaf(p, s, -0.04938272f);
    p = fmaf(p, s, 0.09876543f);
    p = fmaf(p, s, -0.22222222f);
    p = fmaf(p, s, 0.66666667f);
    p = fmaf(p, s, -0.28768207f);
    return fmaxf(x, 0.0f) + p;
}

__device__ __forceinline__ float to_tf32(float x) {
    float r;
    asm("cvt.rna.tf32.f32 %0, %1;" : "=f"(r) : "f"(x));
    return r;
}

// tf32 MMA (node/final kernels)
__device__ __forceinline__ void mma16n8k8(float c[4], const uint32_t a[4],
                                          const uint32_t b[2]) {
    asm volatile(
        "mma.sync.aligned.m16n8k8.row.col.f32.tf32.tf32.f32 "
        "{%0,%1,%2,%3}, {%4,%5,%6,%7}, {%8,%9}, {%0,%1,%2,%3};"
        : "+f"(c[0]), "+f"(c[1]), "+f"(c[2]), "+f"(c[3])
        : "r"(a[0]), "r"(a[1]), "r"(a[2]), "r"(a[3]), "r"(b[0]), "r"(b[1]));
}

// fp16 MMA, fp32 accumulate (edge kernel)
__device__ __forceinline__ void mma16n8k16h(float c[4], const uint32_t a[4],
                                            const uint32_t b[2]) {
    asm volatile(
        "mma.sync.aligned.m16n8k16.row.col.f32.f16.f16.f32 "
        "{%0,%1,%2,%3}, {%4,%5,%6,%7}, {%8,%9}, {%0,%1,%2,%3};"
        : "+f"(c[0]), "+f"(c[1]), "+f"(c[2]), "+f"(c[3])
        : "r"(a[0]), "r"(a[1]), "r"(a[2]), "r"(a[3]), "r"(b[0]), "r"(b[1]));
}

__device__ __forceinline__ void red_add_v4(float* addr, float4 v) {
    asm volatile("red.global.add.v4.f32 [%0], {%1, %2, %3, %4};"
                 :: "l"(addr), "f"(v.x), "f"(v.y), "f"(v.z), "f"(v.w) : "memory");
}

#define BAR_GRP(id) asm volatile("bar.sync %0, 64;" :: "r"(id) : "memory")

#define NT 512       // threads per CTA: 16 warps = 8 groups x 2 warps
#define SA 132       // padded fp32 stride (tf32 path)
#define SH 136       // padded fp16 stride (edge path): word stride 68 -> banks 4*row

__device__ __forceinline__ void zero_acc8(float acc[8][4]) {
    #pragma unroll
    for (int nj = 0; nj < 8; ++nj)
        #pragma unroll
        for (int e = 0; e < 4; ++e) acc[nj][e] = 0.0f;
}

// ==========================================================================
// fp16 edge-kernel helpers
// ==========================================================================

// Weights: row-major [128 x 128] fp32 -> fp16, padded stride SH
__device__ __forceinline__ void load_weights_h(const float* __restrict__ G,
                                               __half* __restrict__ Wh) {
    for (int idx = threadIdx.x; idx < 128 * 32; idx += NT) {
        int n = idx >> 5, q = idx & 31;
        float4 v = *(const float4*)&G[n * 128 + q * 4];
        *(__half2*)&Wh[n * SH + q * 4]     = __floats2half2_rn(v.x, v.y);
        *(__half2*)&Wh[n * SH + q * 4 + 2] = __floats2half2_rn(v.z, v.w);
    }
}

// Group-local load: 16 fp32 rows -> fp16 As rows srow0..+15. 64 threads.
__device__ __forceinline__ void load_rows16_h(const float* __restrict__ G, int grow0,
                                              int nrows, __half* __restrict__ Sm,
                                              int srow0, int tg) {
    #pragma unroll
    for (int i = 0; i < 8; ++i) {
        int idx = tg + i * 64;   // 0..511 float4 slots
        int r = idx >> 5;
        int q = idx & 31;
        float4 v = make_float4(0.f, 0.f, 0.f, 0.f);
        if (grow0 + r < nrows) v = *(const float4*)&G[(size_t)(grow0 + r) * 128 + q * 4];
        *(__half2*)&Sm[(srow0 + r) * SH + q * 4]     = __floats2half2_rn(v.x, v.y);
        *(__half2*)&Sm[(srow0 + r) * SH + q * 4 + 2] = __floats2half2_rn(v.z, v.w);
    }
}

// 16x128x64 fp16 warp GEMM: acc += A(rows mb*16..+15) * W(rows nb*64..+63)^T
__device__ __forceinline__ void warp_gemm_h(const __half* __restrict__ As,
                                            const __half* __restrict__ Wh,
                                            float acc[8][4], int mb, int nb) {
    const int lid = threadIdx.x & 31;
    const int gr = lid >> 2;
    const int gc = lid & 3;
    const __half* ar0 = As + (mb * 16 + gr) * SH + 2 * gc;
    const __half* ar1 = ar0 + 8 * SH;
    const __half* wb  = Wh + (nb * 64 + gr) * SH + 2 * gc;

    #pragma unroll
    for (int c = 0; c < 8; ++c) {
        const int k0 = c * 16;
        uint32_t a[4];
        a[0] = *(const uint32_t*)(ar0 + k0);
        a[1] = *(const uint32_t*)(ar1 + k0);
        a[2] = *(const uint32_t*)(ar0 + k0 + 8);
        a[3] = *(const uint32_t*)(ar1 + k0 + 8);
        #pragma unroll
        for (int nj = 0; nj < 8; ++nj) {
            const __half* wp = wb + nj * 8 * SH + k0;
            uint32_t b[2];
            b[0] = *(const uint32_t*)(wp);
            b[1] = *(const uint32_t*)(wp + 8);
            mma16n8k16h(acc[nj], a, b);
        }
    }
}

// ssp(acc + bias) -> fp16 As rows mb*16..+15, cols nb*64..+63
__device__ __forceinline__ void ssp_writeback_h(__half* __restrict__ Sm,
                                                const float* __restrict__ bias,
                                                float acc[8][4], int mb, int nb) {
    const int lid = threadIdx.x & 31;
    const int gr = lid >> 2;
    const int gc = lid & 3;
    int r0 = mb * 16 + gr;
    #pragma unroll
    for (int nj = 0; nj < 8; ++nj) {
        int c0 = nb * 64 + nj * 8 + 2 * gc;
        float b0 = bias[c0], b1v = bias[c0 + 1];
        *(__half2*)&Sm[r0 * SH + c0] =
            __floats2half2_rn(sspf(acc[nj][0] + b0), sspf(acc[nj][1] + b1v));
        *(__half2*)&Sm[(r0 + 8) * SH + c0] =
            __floats2half2_rn(sspf(acc[nj][2] + b0), sspf(acc[nj][3] + b1v));
    }
}

// ==========================================================================
// Edge kernel (fp16 MMA): 8 independent 2-warp groups, named barriers
// ==========================================================================
#define TILES_PER_CTA 8
#define EGRID 586

// byte offsets in dynamic smem
#define ESMB_SRC 0
#define ESMB_DST 512
#define ESMB_B1 1024
#define ESMB_B2 1536
#define ESMB_AS 2048                       // 128*SH*2 = 34816 B
#define ESMB_W1 (2048 + 34816)
#define ESMB_W2 (2048 + 2 * 34816)
#define ESMB_TOTAL (2048 + 3 * 34816)      // 106496 B

__global__ void __launch_bounds__(NT, 1)
edge_kernel(const float* __restrict__ ea, const int* __restrict__ ei,
            const float* __restrict__ fw1, const float* __restrict__ fb1,
            const float* __restrict__ fw2, const float* __restrict__ fb2) {
    extern __shared__ char smb[];
    int* src_s = (int*)(smb + ESMB_SRC);
    int* dst_s = (int*)(smb + ESMB_DST);
    float* b1s = (float*)(smb + ESMB_B1);
    float* b2s = (float*)(smb + ESMB_B2);
    __half* As  = (__half*)(smb + ESMB_AS);
    __half* W1h = (__half*)(smb + ESMB_W1);
    __half* W2h = (__half*)(smb + ESMB_W2);

    const int tid = threadIdx.x;
    const int mb = tid >> 6;          // group 0..7: rows mb*16..+15
    const int nb = (tid >> 5) & 1;    // warp-in-group: cols nb*64..+63
    const int tg = tid & 63;          // thread-in-group
    const int bar = mb + 1;           // named barrier ids 1..8

    load_weights_h(fw1, W1h);
    load_weights_h(fw2, W2h);
    if (tid < 128) {
        b1s[tid] = fb1[tid];
        b2s[tid] = fb2[tid];
    }
    __syncthreads();

    for (int it = 0; it < TILES_PER_CTA; ++it) {
        const int row0 = (blockIdx.x * TILES_PER_CTA + it) * 128;
        if (row0 >= N_EDGES) break;

        // group-local loads: 16 ea rows (fp16) + 16 index pairs
        load_rows16_h(ea, row0 + mb * 16, N_EDGES, As, mb * 16, tg);
        if (tg < 16) {
            int e = row0 + mb * 16 + tg;
            src_s[mb * 16 + tg] = (e < N_EDGES) ? ei[e] : 0;
            dst_s[mb * 16 + tg] = (e < N_EDGES) ? ei[N_EDGES + e] : 0;
        }
        BAR_GRP(bar);

        float acc[8][4];

        zero_acc8(acc);
        warp_gemm_h(As, W1h, acc, mb, nb);          // Y1 = ea @ W1^T
        BAR_GRP(bar);

        ssp_writeback_h(As, b1s, acc, mb, nb);      // Z = fp16(ssp(Y1+b1))
        BAR_GRP(bar);

        zero_acc8(acc);
        warp_gemm_h(As, W2h, acc, mb, nb);          // Y2 = Z @ W2^T
        BAR_GRP(bar);

        ssp_writeback_h(As, b2s, acc, mb, nb);      // W = fp16(ssp(Y2+b2))
        BAR_GRP(bar);

        // epilogue: group's 16 rows; msg = h[src]*W; red.add -> agg[dst]
        {
            const int hw = tg >> 4;     // 0..3 -> 4 rows each
            const int l16 = tg & 15;    // 8-col slice
            #pragma unroll
            for (int j = 0; j < 4; ++j) {
                int m = mb * 16 + hw * 4 + j;
                int e = row0 + m;
                if (e < N_EDGES) {
                    int s = src_s[m];
                    int d = dst_s[m];
                    // 8 fp16 W values: byte off = m*272 + 16*l16 (16B aligned)
                    uint4 wu = *(const uint4*)&As[m * SH + l16 * 8];
                    const __half2* wh = (const __half2*)&wu;
                    float2 w0 = __half22float2(wh[0]);
                    float2 w1 = __half22float2(wh[1]);
                    float2 w2 = __half22float2(wh[2]);
                    float2 w3 = __half22float2(wh[3]);
                    const float* hp = &g_h[(size_t)s * 128 + l16 * 8];
                    float* ap = &g_agg[(size_t)d * 128 + l16 * 8];
                    float4 h0 = *(const float4*)hp;
                    float4 h1 = *(const float4*)(hp + 4);
                    red_add_v4(ap, make_float4(w0.x * h0.x, w0.y * h0.y,
                                               w1.x * h0.z, w1.y * h0.w));
                    red_add_v4(ap + 4, make_float4(w2.x * h1.x, w2.y * h1.y,
                                                   w3.x * h1.z, w3.y * h1.w));
                }
            }
        }
        BAR_GRP(bar);  // As reads done before next tile's load
    }
}

// ==========================================================================
// tf32 machinery for node/final kernels (unchanged, proven)
// ==========================================================================
__device__ __forceinline__ int wcol(int k, int n) {
    int pk = (k & ~15) | ((k & 3) << 2) | ((k >> 2) & 3);
    return pk ^ ((n & 1) << 4);
}

__device__ __forceinline__ void load_weights_packed(const float* __restrict__ G,
                                                    float* __restrict__ Wp) {
    for (int idx = threadIdx.x; idx < 128 * 32; idx += NT) {
        int n = idx >> 5, t = idx & 31;
        float4 v = *(const float4*)&G[n * 128 + t * 4];
        float vv[4] = {to_tf32(v.x), to_tf32(v.y), to_tf32(v.z), to_tf32(v.w)};
        #pragma unroll
        for (int i = 0; i < 4; ++i) Wp[n * 128 + wcol(t * 4 + i, n)] = vv[i];
    }
}

__device__ __forceinline__ void load_rows16(const float* __restrict__ G, int grow0,
                                            int nrows, float* __restrict__ Sm,
                                            int srow0, int tg) {
    #pragma unroll
    for (int i = 0; i < 8; ++i) {
        int idx = tg + i * 64;
        int r = idx >> 5;
        int q = idx & 31;
        float4 v = make_float4(0.f, 0.f, 0.f, 0.f);
        if (grow0 + r < nrows) v = *(const float4*)&G[(size_t)(grow0 + r) * 128 + q * 4];
        v.x = to_tf32(v.x); v.y = to_tf32(v.y); v.z = to_tf32(v.z); v.w = to_tf32(v.w);
        *(float4*)&Sm[(srow0 + r) * SA + q * 4] = v;
    }
}

__device__ __forceinline__ void warp_gemm(const float* __restrict__ As,
                                          const float* __restrict__ Wp,
                                          float acc[8][4], int mb, int nb) {
    const int lid = threadIdx.x & 31;
    const int gr = lid >> 2;
    const int gc = lid & 3;
    const float* abase = As + (mb * 16 + gr) * SA + gc;
    const int nrow0 = nb * 64 + gr;
    const int nxor = (gr & 1) << 4;

    #pragma unroll
    for (int c = 0; c < 8; ++c) {
        const int k0 = c * 16;
        const float* ap0 = abase + k0;
        const float* ap1 = ap0 + 8 * SA;
        uint32_t a0[4], a1[4];
        a0[0] = __float_as_uint(ap0[0]);
        a0[1] = __float_as_uint(ap1[0]);
        a0[2] = __float_as_uint(ap0[4]);
        a0[3] = __float_as_uint(ap1[4]);
        a1[0] = __float_as_uint(ap0[8]);
        a1[1] = __float_as_uint(ap1[8]);
        a1[2] = __float_as_uint(ap0[12]);
        a1[3] = __float_as_uint(ap1[12]);
        #pragma unroll
        for (int nj = 0; nj < 8; ++nj) {
            const int n = nrow0 + 8 * nj;
            float4 bv = *(const float4*)&Wp[n * 128 + ((k0 + gc * 4) ^ nxor)];
            uint32_t b0[2] = {__float_as_uint(bv.x), __float_as_uint(bv.y)};
            uint32_t b1[2] = {__float_as_uint(bv.z), __float_as_uint(bv.w)};
            mma16n8k8(acc[nj], a0, b0);
            mma16n8k8(acc[nj], a1, b1);
        }
    }
}

__device__ __forceinline__ void ssp_writeback(float* __restrict__ Sm,
                                              const float* __restrict__ bias,
                                              float acc[8][4], int mb, int nb,
                                              bool round_tf32) {
    const int lid = threadIdx.x & 31;
    const int gr = lid >> 2;
    const int gc = lid & 3;
    int r0 = mb * 16 + gr;
    #pragma unroll
    for (int nj = 0; nj < 8; ++nj) {
        int c0 = nb * 64 + nj * 8 + 2 * gc;
        float b0 = bias ? bias[c0] : 0.0f;
        float b1v = bias ? bias[c0 + 1] : 0.0f;
        float2 lo, hi;
        lo.x = sspf(acc[nj][0] + b0);
        lo.y = sspf(acc[nj][1] + b1v);
        hi.x = sspf(acc[nj][2] + b0);
        hi.y = sspf(acc[nj][3] + b1v);
        if (round_tf32) {
            lo.x = to_tf32(lo.x); lo.y = to_tf32(lo.y);
            hi.x = to_tf32(hi.x); hi.y = to_tf32(hi.y);
        }
        *(float2*)&Sm[r0 * SA + c0] = lo;
        *(float2*)&Sm[(r0 + 8) * SA + c0] = hi;
    }
}

// ==========================================================================
// Node h kernel (persistent, grouped, tf32): h = x @ fc1^T ; zero g_agg
// ==========================================================================
#define NODE_TILES 2
#define NODE_GRID 196   // 196*2 = 392 >= 391

#define NSM_AS 0
#define NSM_W (128 * SA)
#define NSM_FLOATS (128 * SA + 16384)

__global__ void __launch_bounds__(NT, 1)
node_h_kernel(const float* __restrict__ x, const float* __restrict__ fc1_w) {
    extern __shared__ float sm[];
    float* As = &sm[NSM_AS];
    float* Wp = &sm[NSM_W];

    const int tid = threadIdx.x;
    const int mb = tid >> 6;
    const int nb = (tid >> 5) & 1;
    const int tg = tid & 63;
    const int bar = mb + 1;
    const int lid = tid & 31;
    const int gr = lid >> 2;
    const int gc = lid & 3;

    load_weights_packed(fc1_w, Wp);
    __syncthreads();

    for (int it = 0; it < NODE_TILES; ++it) {
        const int row0 = (blockIdx.x * NODE_TILES + it) * 128;
        if (row0 >= N_NODES) break;

        load_rows16(x, row0 + mb * 16, N_NODES, As, mb * 16, tg);
        BAR_GRP(bar);

        float acc[8][4];
        zero_acc8(acc);
        warp_gemm(As, Wp, acc, mb, nb);

        int r0 = row0 + mb * 16 + gr;
        #pragma unroll
        for (int nj = 0; nj < 8; ++nj) {
            int c0 = nb * 64 + nj * 8 + 2 * gc;
            if (r0 < N_NODES)
                *(float2*)&g_h[(size_t)r0 * 128 + c0] =
                    make_float2(acc[nj][0], acc[nj][1]);
            if (r0 + 8 < N_NODES)
                *(float2*)&g_h[(size_t)(r0 + 8) * 128 + c0] =
                    make_float2(acc[nj][2], acc[nj][3]);
        }

        const float4 z4 = make_float4(0.f, 0.f, 0.f, 0.f);
        #pragma unroll
        for (int i = 0; i < 8; ++i) {
            int idx = tg + i * 64;
            int r = row0 + mb * 16 + (idx >> 5);
            int q = idx & 31;
            if (r < N_NODES) *(float4*)&g_agg[(size_t)r * 128 + q * 4] = z4;
        }
        BAR_GRP(bar);
    }
}

// ==========================================================================
// Final kernel (persistent, grouped, tf32): out = ssp(agg @ s_w1^T) @ s_w2^T
// ==========================================================================
#define FSM_AS 0
#define FSM_W1 (128 * SA)
#define FSM_W2 (128 * SA + 16384)
#define FSM_FLOATS (128 * SA + 32768)

__global__ void __launch_bounds__(NT, 1)
final_kernel(const float* __restrict__ sw1, const float* __restrict__ sw2,
             float* __restrict__ out) {
    extern __shared__ float sm[];
    float* As = &sm[FSM_AS];
    float* W1p = &sm[FSM_W1];
    float* W2p = &sm[FSM_W2];

    const int tid = threadIdx.x;
    const int mb = tid >> 6;
    const int nb = (tid >> 5) & 1;
    const int tg = tid & 63;
    const int bar = mb + 1;
    const int lid = tid & 31;
    const int gr = lid >> 2;
    const int gc = lid & 3;

    load_weights_packed(sw1, W1p);
    load_weights_packed(sw2, W2p);
    __syncthreads();

    for (int it = 0; it < NODE_TILES; ++it) {
        const int row0 = (blockIdx.x * NODE_TILES + it) * 128;
        if (row0 >= N_NODES) break;

        load_rows16(g_agg, row0 + mb * 16, N_NODES, As, mb * 16, tg);
        BAR_GRP(bar);

        float acc[8][4];
        zero_acc8(acc);
        warp_gemm(As, W1p, acc, mb, nb);
        BAR_GRP(bar);

        ssp_writeback(As, (const float*)nullptr, acc, mb, nb, true);
        BAR_GRP(bar);

        zero_acc8(acc);
        warp_gemm(As, W2p, acc, mb, nb);

        int r0 = row0 + mb * 16 + gr;
        #pragma unroll
        for (int nj = 0; nj < 8; ++nj) {
            int c0 = nb * 64 + nj * 8 + 2 * gc;
            if (r0 < N_NODES)
                *(float2*)&out[(size_t)r0 * 128 + c0] =
                    make_float2(acc[nj][0], acc[nj][1]);
            if (r0 + 8 < N_NODES)
                *(float2*)&out[(size_t)(r0 + 8) * 128 + c0] =
                    make_float2(acc[nj][2], acc[nj][3]);
        }
        BAR_GRP(bar);
    }
}

// ==========================================================================
extern "C" void kernel_launch(void* const* d_in, const int* in_sizes, int n_in,
                              void* d_out, int out_size) {
    const float* x = (const float*)d_in[0];
    const float* ea = (const float*)d_in[1];
    const int* ei = (const int*)d_in[2];
    const float* fc1w = (const float*)d_in[3];
    const float* fw1 = (const float*)d_in[4];
    const float* fb1 = (const float*)d_in[5];
    const float* fw2 = (const float*)d_in[6];
    const float* fb2 = (const float*)d_in[7];
    const float* sw1 = (const float*)d_in[8];
    const float* sw2 = (const float*)d_in[9];
    float* out = (float*)d_out;

    const size_t sh_edge = ESMB_TOTAL;
    const size_t sh_node = (size_t)NSM_FLOATS * sizeof(float);
    const size_t sh_final = (size_t)FSM_FLOATS * sizeof(float);

    cudaFuncSetAttribute(edge_kernel, cudaFuncAttributeMaxDynamicSharedMemorySize, (int)sh_edge);
    cudaFuncSetAttribute(node_h_kernel, cudaFuncAttributeMaxDynamicSharedMemorySize, (int)sh_node);
    cudaFuncSetAttribute(final_kernel, cudaFuncAttributeMaxDynamicSharedMemorySize, (int)sh_final);

    node_h_kernel<<<NODE_GRID, NT, sh_node>>>(x, fc1w);
    edge_kernel<<<EGRID, NT, sh_edge>>>(ea, ei, fw1, fb1, fw2, fb2);
    final_kernel<<<NODE_GRID, NT, sh_final>>>(sw1, sw2, out);
}